// round 1
// baseline (speedup 1.0000x reference)
#include <cuda_runtime.h>
#include <math.h>

#define NN     50000
#define NEDGE  600000
#define HDIM   128
#define NPASS  5
#define LN_EPS 1e-6f

#define NODE_TILES ((NN + 63) / 64)   // 782
#define EDGE_TILES (NEDGE / 64)       // 9375 (exact)

// Persistent device scratch (static allocation is allowed; cudaMalloc is not)
__device__ float g_n[NN * HDIM];                 // node features (updated in place each pass)
__device__ float g_agg[NN * HDIM];               // per-pass aggregation target
__device__ float g_emsg[NEDGE * HDIM];           // precomputed e @ W_msg[128:256,:]

// ---------------------------------------------------------------------------
// Register-tiled GEMM micro-step.
// Block = 256 threads = 8 warps. Tile = 64 rows x 128 cols.
// Warp ty owns rows [ty*8, ty*8+8); lane tx owns cols [tx*4, tx*4+4).
// A_s: [64][LDA] row-major (scalar broadcast reads), B_s: [KC][128] (float4 reads).
// ---------------------------------------------------------------------------
template<int KC, int LDA>
__device__ __forceinline__ void gemm_step(const float* __restrict__ A_s,
                                          const float* __restrict__ B_s,
                                          int m0, int j, float acc[8][4]) {
#pragma unroll 8
    for (int kk = 0; kk < KC; kk++) {
        float4 b = *(const float4*)(B_s + kk * HDIM + j);
#pragma unroll
        for (int r = 0; r < 8; r++) {
            float a = A_s[(m0 + r) * LDA + kk];
            acc[r][0] = fmaf(a, b.x, acc[r][0]);
            acc[r][1] = fmaf(a, b.y, acc[r][1]);
            acc[r][2] = fmaf(a, b.z, acc[r][2]);
            acc[r][3] = fmaf(a, b.w, acc[r][3]);
        }
    }
}

// ---------------------------------------------------------------------------
// Node encoder: n = relu(x @ W0 + b0) @ W1 + b1      x: [NN,32]
// ---------------------------------------------------------------------------
__global__ void k_node_enc(const float* __restrict__ x,
                           const float* __restrict__ W0, const float* __restrict__ b0,
                           const float* __restrict__ W1, const float* __restrict__ b1) {
    extern __shared__ float sm[];
    float* h_s = sm;                 // [64][132]
    float* B_s = sm + 64 * 132;      // [32][128]
    float* A_s = sm;                 // union with h_s, [64][33]

    const int tid = threadIdx.x;
    const int ty = tid >> 5, tx = tid & 31;
    const int m0 = ty * 8;
    const int j  = tx * 4;
    const int row0 = blockIdx.x * 64;

    // ---- layer 1: K = 32 ----
#pragma unroll
    for (int i = 0; i < 8; i++) {
        int idx = tid + i * 256;
        int m = idx >> 5, kk = idx & 31;
        int gr = row0 + m;
        A_s[m * 33 + kk] = (gr < NN) ? x[gr * 32 + kk] : 0.f;
    }
#pragma unroll
    for (int i = 0; i < 16; i++) {
        int idx = tid + i * 256;
        B_s[idx] = W0[idx];          // 32x128
    }
    __syncthreads();

    float acc[8][4];
    {
        float4 bv = *(const float4*)(b0 + j);
#pragma unroll
        for (int r = 0; r < 8; r++) { acc[r][0]=bv.x; acc[r][1]=bv.y; acc[r][2]=bv.z; acc[r][3]=bv.w; }
    }
    gemm_step<32, 33>(A_s, B_s, m0, j, acc);
    __syncthreads();                 // A_s reads done (union with h_s)

#pragma unroll
    for (int r = 0; r < 8; r++) {
        float4 h;
        h.x = fmaxf(acc[r][0], 0.f); h.y = fmaxf(acc[r][1], 0.f);
        h.z = fmaxf(acc[r][2], 0.f); h.w = fmaxf(acc[r][3], 0.f);
        *(float4*)(h_s + (m0 + r) * 132 + j) = h;
    }

    // ---- layer 2: K = 128 ----
    float o[8][4];
    {
        float4 bv = *(const float4*)(b1 + j);
#pragma unroll
        for (int r = 0; r < 8; r++) { o[r][0]=bv.x; o[r][1]=bv.y; o[r][2]=bv.z; o[r][3]=bv.w; }
    }
    for (int c = 0; c < 4; c++) {
        __syncthreads();
#pragma unroll
        for (int i = 0; i < 16; i++) {
            int idx = tid + i * 256;
            B_s[idx] = W1[c * 32 * 128 + idx];
        }
        __syncthreads();
        gemm_step<32, 132>(h_s + c * 32, B_s, m0, j, o);
    }
#pragma unroll
    for (int r = 0; r < 8; r++) {
        int gr = row0 + m0 + r;
        if (gr < NN)
            *(float4*)(g_n + gr * HDIM + j) = make_float4(o[r][0], o[r][1], o[r][2], o[r][3]);
    }
}

// ---------------------------------------------------------------------------
// Edge encoder fused with message-bottom projection:
//   e  = relu(x @ W0 + b0) @ W1 + b1        x: [NE,16]
//   g_emsg = e @ W_msg[128:256, :]          (loop-invariant part of messages)
// ---------------------------------------------------------------------------
__global__ void k_edge_enc(const float* __restrict__ x,
                           const float* __restrict__ W0, const float* __restrict__ b0,
                           const float* __restrict__ W1, const float* __restrict__ b1,
                           const float* __restrict__ Wm) {
    extern __shared__ float sm[];
    float* h_s = sm;                 // [64][132]
    float* B_s = sm + 64 * 132;      // [32][128]
    float* A_s = sm;                 // union, [64][17]

    const int tid = threadIdx.x;
    const int ty = tid >> 5, tx = tid & 31;
    const int m0 = ty * 8;
    const int j  = tx * 4;
    const int row0 = blockIdx.x * 64;

    // ---- layer 1: K = 16 ----
#pragma unroll
    for (int i = 0; i < 4; i++) {
        int idx = tid + i * 256;
        int m = idx >> 4, kk = idx & 15;
        A_s[m * 17 + kk] = x[(row0 + m) * 16 + kk];
    }
#pragma unroll
    for (int i = 0; i < 8; i++) {
        int idx = tid + i * 256;
        B_s[idx] = W0[idx];          // 16x128
    }
    __syncthreads();

    float acc[8][4];
    {
        float4 bv = *(const float4*)(b0 + j);
#pragma unroll
        for (int r = 0; r < 8; r++) { acc[r][0]=bv.x; acc[r][1]=bv.y; acc[r][2]=bv.z; acc[r][3]=bv.w; }
    }
    gemm_step<16, 17>(A_s, B_s, m0, j, acc);
    __syncthreads();

#pragma unroll
    for (int r = 0; r < 8; r++) {
        float4 h;
        h.x = fmaxf(acc[r][0], 0.f); h.y = fmaxf(acc[r][1], 0.f);
        h.z = fmaxf(acc[r][2], 0.f); h.w = fmaxf(acc[r][3], 0.f);
        *(float4*)(h_s + (m0 + r) * 132 + j) = h;
    }

    // ---- layer 2: K = 128 ----
    float a2[8][4];
    {
        float4 bv = *(const float4*)(b1 + j);
#pragma unroll
        for (int r = 0; r < 8; r++) { a2[r][0]=bv.x; a2[r][1]=bv.y; a2[r][2]=bv.z; a2[r][3]=bv.w; }
    }
    for (int c = 0; c < 4; c++) {
        __syncthreads();
#pragma unroll
        for (int i = 0; i < 16; i++) {
            int idx = tid + i * 256;
            B_s[idx] = W1[c * 32 * 128 + idx];
        }
        __syncthreads();
        gemm_step<32, 132>(h_s + c * 32, B_s, m0, j, a2);
    }
    __syncthreads();
#pragma unroll
    for (int r = 0; r < 8; r++)
        *(float4*)(h_s + (m0 + r) * 132 + j) = make_float4(a2[r][0], a2[r][1], a2[r][2], a2[r][3]);

    // ---- layer 3: e @ W_msg_bottom, K = 128 ----
    float a3[8][4];
#pragma unroll
    for (int r = 0; r < 8; r++) { a3[r][0]=0.f; a3[r][1]=0.f; a3[r][2]=0.f; a3[r][3]=0.f; }
    for (int c = 0; c < 4; c++) {
        __syncthreads();
#pragma unroll
        for (int i = 0; i < 16; i++) {
            int idx = tid + i * 256;
            B_s[idx] = Wm[128 * 128 + c * 32 * 128 + idx];   // bottom half of W_msg
        }
        __syncthreads();
        gemm_step<32, 132>(h_s + c * 32, B_s, m0, j, a3);
    }
#pragma unroll
    for (int r = 0; r < 8; r++)
        *(float4*)(g_emsg + (row0 + m0 + r) * HDIM + j) =
            make_float4(a3[r][0], a3[r][1], a3[r][2], a3[r][3]);
}

// ---------------------------------------------------------------------------
// Per-pass edge message: gather n[sender] -> GEMM with W_msg_top -> + g_emsg
// -> atomic scatter-add into g_agg[receiver]
// ---------------------------------------------------------------------------
__global__ void k_edge_msg(const float* __restrict__ Wm,
                           const int* __restrict__ senders,
                           const int* __restrict__ recvs) {
    extern __shared__ float sm[];
    float* A_s = sm;                         // [64][33]
    float* B_s = sm + 64 * 33;               // [32][128]
    int*   s_idx = (int*)(B_s + 32 * 128);   // [64]
    int*   r_idx = s_idx + 64;               // [64]

    const int tid = threadIdx.x;
    const int ty = tid >> 5, tx = tid & 31;
    const int m0 = ty * 8;
    const int j  = tx * 4;
    const int e0 = blockIdx.x * 64;

    if (tid < 64)       s_idx[tid]      = senders[e0 + tid];
    else if (tid < 128) r_idx[tid - 64] = recvs[e0 + tid - 64];

    float acc[8][4];
#pragma unroll
    for (int r = 0; r < 8; r++) { acc[r][0]=0.f; acc[r][1]=0.f; acc[r][2]=0.f; acc[r][3]=0.f; }

    for (int c = 0; c < 4; c++) {
        __syncthreads();
#pragma unroll
        for (int i = 0; i < 8; i++) {
            int idx = tid + i * 256;
            int m = idx >> 5, kk = idx & 31;
            A_s[m * 33 + kk] = g_n[s_idx[m] * HDIM + c * 32 + kk];   // gathered sender rows
        }
#pragma unroll
        for (int i = 0; i < 16; i++) {
            int idx = tid + i * 256;
            B_s[idx] = Wm[c * 32 * 128 + idx];                        // top half of W_msg
        }
        __syncthreads();
        gemm_step<32, 33>(A_s, B_s, m0, j, acc);
    }

#pragma unroll
    for (int r = 0; r < 8; r++) {
        int e = e0 + m0 + r;
        float4 em = *(const float4*)(g_emsg + e * HDIM + j);
        float* dst = g_agg + r_idx[m0 + r] * HDIM + j;
        atomicAdd(dst + 0, acc[r][0] + em.x);
        atomicAdd(dst + 1, acc[r][1] + em.y);
        atomicAdd(dst + 2, acc[r][2] + em.z);
        atomicAdd(dst + 3, acc[r][3] + em.w);
    }
}

// ---------------------------------------------------------------------------
// Per-pass node update:
//   h = relu(concat(n, agg) @ W0 + b0); o = h @ W1 + b1; r = n @ Wn
//   n = LayerNorm(o + r) * g + b      (in place; blocks touch only own rows)
// ---------------------------------------------------------------------------
__global__ void k_node_upd(const float* __restrict__ W0, const float* __restrict__ b0,
                           const float* __restrict__ W1, const float* __restrict__ b1,
                           const float* __restrict__ Wn,
                           const float* __restrict__ lng, const float* __restrict__ lnb) {
    extern __shared__ float sm[];
    float* h_s = sm;                 // [64][132]
    float* B_s = sm + 64 * 132;      // [32][128]
    float* A_s = sm;                 // union, [64][33]

    const int tid = threadIdx.x;
    const int ty = tid >> 5, tx = tid & 31;
    const int m0 = ty * 8;
    const int j  = tx * 4;
    const int row0 = blockIdx.x * 64;

    // ---- hidden layer: K = 256 (n rows then agg rows) ----
    float acc[8][4];
    {
        float4 bv = *(const float4*)(b0 + j);
#pragma unroll
        for (int r = 0; r < 8; r++) { acc[r][0]=bv.x; acc[r][1]=bv.y; acc[r][2]=bv.z; acc[r][3]=bv.w; }
    }
    for (int c = 0; c < 8; c++) {
        const float* src = (c < 4) ? g_n : g_agg;
        int koff = (c & 3) * 32;
        __syncthreads();
#pragma unroll
        for (int i = 0; i < 8; i++) {
            int idx = tid + i * 256;
            int m = idx >> 5, kk = idx & 31;
            int gr = row0 + m;
            A_s[m * 33 + kk] = (gr < NN) ? src[gr * HDIM + koff + kk] : 0.f;
        }
#pragma unroll
        for (int i = 0; i < 16; i++) {
            int idx = tid + i * 256;
            B_s[idx] = W0[c * 32 * 128 + idx];
        }
        __syncthreads();
        gemm_step<32, 33>(A_s, B_s, m0, j, acc);
    }
    __syncthreads();
#pragma unroll
    for (int r = 0; r < 8; r++) {
        float4 h;
        h.x = fmaxf(acc[r][0], 0.f); h.y = fmaxf(acc[r][1], 0.f);
        h.z = fmaxf(acc[r][2], 0.f); h.w = fmaxf(acc[r][3], 0.f);
        *(float4*)(h_s + (m0 + r) * 132 + j) = h;
    }

    // ---- output layer: K = 128 ----
    float o[8][4];
    {
        float4 bv = *(const float4*)(b1 + j);
#pragma unroll
        for (int r = 0; r < 8; r++) { o[r][0]=bv.x; o[r][1]=bv.y; o[r][2]=bv.z; o[r][3]=bv.w; }
    }
    for (int c = 0; c < 4; c++) {
        __syncthreads();
#pragma unroll
        for (int i = 0; i < 16; i++) {
            int idx = tid + i * 256;
            B_s[idx] = W1[c * 32 * 128 + idx];
        }
        __syncthreads();
        gemm_step<32, 132>(h_s + c * 32, B_s, m0, j, o);
    }

    // ---- residual: n @ Wn, K = 128 (A_s reuses h_s region after reads done) ----
    float rr[8][4];
#pragma unroll
    for (int r = 0; r < 8; r++) { rr[r][0]=0.f; rr[r][1]=0.f; rr[r][2]=0.f; rr[r][3]=0.f; }
    for (int c = 0; c < 4; c++) {
        __syncthreads();
#pragma unroll
        for (int i = 0; i < 8; i++) {
            int idx = tid + i * 256;
            int m = idx >> 5, kk = idx & 31;
            int gr = row0 + m;
            A_s[m * 33 + kk] = (gr < NN) ? g_n[gr * HDIM + c * 32 + kk] : 0.f;
        }
#pragma unroll
        for (int i = 0; i < 16; i++) {
            int idx = tid + i * 256;
            B_s[idx] = Wn[c * 32 * 128 + idx];
        }
        __syncthreads();
        gemm_step<32, 33>(A_s, B_s, m0, j, rr);
    }

    // ---- LayerNorm epilogue (row stats via warp shuffles; warp owns full rows)
    float4 gv  = *(const float4*)(lng + j);
    float4 bbv = *(const float4*)(lnb + j);
#pragma unroll
    for (int r = 0; r < 8; r++) {
        float t0 = o[r][0] + rr[r][0];
        float t1 = o[r][1] + rr[r][1];
        float t2 = o[r][2] + rr[r][2];
        float t3 = o[r][3] + rr[r][3];
        float s1 = t0 + t1 + t2 + t3;
        float s2 = t0*t0 + t1*t1 + t2*t2 + t3*t3;
#pragma unroll
        for (int off = 16; off > 0; off >>= 1) {
            s1 += __shfl_xor_sync(0xffffffffu, s1, off);
            s2 += __shfl_xor_sync(0xffffffffu, s2, off);
        }
        float mu  = s1 * (1.f / 128.f);
        float var = s2 * (1.f / 128.f) - mu * mu;
        float inv = rsqrtf(var + LN_EPS);
        int gr = row0 + m0 + r;
        if (gr < NN) {
            float4 out;
            out.x = (t0 - mu) * inv * gv.x + bbv.x;
            out.y = (t1 - mu) * inv * gv.y + bbv.y;
            out.z = (t2 - mu) * inv * gv.z + bbv.z;
            out.w = (t3 - mu) * inv * gv.w + bbv.w;
            *(float4*)(g_n + gr * HDIM + j) = out;
        }
    }
}

// ---------------------------------------------------------------------------
// Decoder: out = relu(n @ W0 + b0) @ W1 + b1       out: [NN,2]
// ---------------------------------------------------------------------------
__global__ void k_dec(const float* __restrict__ W0, const float* __restrict__ b0,
                      const float* __restrict__ W1, const float* __restrict__ b1,
                      float* __restrict__ out) {
    extern __shared__ float sm[];
    float* h_s  = sm;                 // [64][132]
    float* B_s  = sm + 64 * 132;      // [32][128]
    float* A_s  = sm;                 // union, [64][33]
    float* w1_s = B_s + 32 * 128;     // [128*2]
    float* b1_s = w1_s + 256;         // [2]

    const int tid = threadIdx.x;
    const int ty = tid >> 5, tx = tid & 31;
    const int m0 = ty * 8;
    const int j  = tx * 4;
    const int row0 = blockIdx.x * 64;

    float acc[8][4];
    {
        float4 bv = *(const float4*)(b0 + j);
#pragma unroll
        for (int r = 0; r < 8; r++) { acc[r][0]=bv.x; acc[r][1]=bv.y; acc[r][2]=bv.z; acc[r][3]=bv.w; }
    }
    for (int c = 0; c < 4; c++) {
        __syncthreads();
#pragma unroll
        for (int i = 0; i < 8; i++) {
            int idx = tid + i * 256;
            int m = idx >> 5, kk = idx & 31;
            int gr = row0 + m;
            A_s[m * 33 + kk] = (gr < NN) ? g_n[gr * HDIM + c * 32 + kk] : 0.f;
        }
#pragma unroll
        for (int i = 0; i < 16; i++) {
            int idx = tid + i * 256;
            B_s[idx] = W0[c * 32 * 128 + idx];
        }
        __syncthreads();
        gemm_step<32, 33>(A_s, B_s, m0, j, acc);
    }
    __syncthreads();
#pragma unroll
    for (int r = 0; r < 8; r++) {
        float4 h;
        h.x = fmaxf(acc[r][0], 0.f); h.y = fmaxf(acc[r][1], 0.f);
        h.z = fmaxf(acc[r][2], 0.f); h.w = fmaxf(acc[r][3], 0.f);
        *(float4*)(h_s + (m0 + r) * 132 + j) = h;
    }
    w1_s[tid] = W1[tid];              // 256 floats, blockDim == 256
    if (tid < 2) b1_s[tid] = b1[tid];
    __syncthreads();

    if (tid < 128) {
        int row = tid >> 1, c = tid & 1;
        float s = b1_s[c];
#pragma unroll 8
        for (int k = 0; k < 128; k++)
            s = fmaf(h_s[row * 132 + k], w1_s[k * 2 + c], s);
        int gr = row0 + row;
        if (gr < NN) out[gr * 2 + c] = s;
    }
}

__global__ void k_zero_agg() {
    int i = blockIdx.x * blockDim.x + threadIdx.x;
    if (i < NN * HDIM / 4)
        ((float4*)g_agg)[i] = make_float4(0.f, 0.f, 0.f, 0.f);
}

// ---------------------------------------------------------------------------
extern "C" void kernel_launch(void* const* d_in, const int* in_sizes, int n_in,
                              void* d_out, int out_size) {
    const float* nodes   = (const float*)d_in[0];
    const float* edges   = (const float*)d_in[1];
    const int*   senders = (const int*)  d_in[2];
    const int*   recvs   = (const int*)  d_in[3];
    const float* enW0 = (const float*)d_in[4];
    const float* enb0 = (const float*)d_in[5];
    const float* enW1 = (const float*)d_in[6];
    const float* enb1 = (const float*)d_in[7];
    const float* eeW0 = (const float*)d_in[8];
    const float* eeb0 = (const float*)d_in[9];
    const float* eeW1 = (const float*)d_in[10];
    const float* eeb1 = (const float*)d_in[11];
    const float* Wmsg = (const float*)d_in[12];
    const float* nW0  = (const float*)d_in[13];
    const float* nb0  = (const float*)d_in[14];
    const float* nW1  = (const float*)d_in[15];
    const float* nb1  = (const float*)d_in[16];
    const float* Wnode= (const float*)d_in[17];
    const float* lng  = (const float*)d_in[18];
    const float* lnb  = (const float*)d_in[19];
    const float* dW0  = (const float*)d_in[20];
    const float* db0  = (const float*)d_in[21];
    const float* dW1  = (const float*)d_in[22];
    const float* db1  = (const float*)d_in[23];
    float* out = (float*)d_out;

    const int SM_BIG = (64 * 132 + 32 * 128) * 4;              // 50176 B
    const int SM_MSG = (64 * 33 + 32 * 128) * 4 + 128 * 4;     // 25856 B
    const int SM_DEC = (64 * 132 + 32 * 128 + 256 + 2) * 4;    // 51208 B

    cudaFuncSetAttribute(k_node_enc, cudaFuncAttributeMaxDynamicSharedMemorySize, SM_BIG);
    cudaFuncSetAttribute(k_edge_enc, cudaFuncAttributeMaxDynamicSharedMemorySize, SM_BIG);
    cudaFuncSetAttribute(k_edge_msg, cudaFuncAttributeMaxDynamicSharedMemorySize, SM_MSG);
    cudaFuncSetAttribute(k_node_upd, cudaFuncAttributeMaxDynamicSharedMemorySize, SM_BIG);
    cudaFuncSetAttribute(k_dec,      cudaFuncAttributeMaxDynamicSharedMemorySize, SM_DEC);

    k_node_enc<<<NODE_TILES, 256, SM_BIG>>>(nodes, enW0, enb0, enW1, enb1);
    k_edge_enc<<<EDGE_TILES, 256, SM_BIG>>>(edges, eeW0, eeb0, eeW1, eeb1, Wmsg);

    for (int p = 0; p < NPASS; p++) {
        k_zero_agg<<<(NN * HDIM / 4 + 255) / 256, 256>>>();
        k_edge_msg<<<EDGE_TILES, 256, SM_MSG>>>(Wmsg, senders, recvs);
        k_node_upd<<<NODE_TILES, 256, SM_BIG>>>(nW0, nb0, nW1, nb1, Wnode, lng, lnb);
    }

    k_dec<<<NODE_TILES, 256, SM_DEC>>>(dW0, db0, dW1, db1, out);
}

// round 2
// speedup vs baseline: 2.2684x; 2.2684x over previous
#include <cuda_runtime.h>
#include <math.h>

#define NN     50000
#define NEDGE  600000
#define HDIM   128
#define NPASS  5
#define LN_EPS 1e-6f

#define NODE_TILES ((NN + 63) / 64)   // 782
#define EDGE_TILES (NEDGE / 64)       // 9375 (exact)

// Persistent device scratch
__device__ float g_n[NN * HDIM];                 // node features
__device__ float g_mn[NN * HDIM];                // m_n = n @ W_msg_top  (per pass)
__device__ float g_agg[NN * HDIM];               // aggregation target
__device__ float g_emsg[NEDGE * HDIM];           // e @ W_msg_bottom (loop-invariant)
__device__ float g_Wc[HDIM * HDIM];              // W1_edge @ W_msg_bottom (folded)
__device__ float g_bc[HDIM];                     // b1_edge @ W_msg_bottom

// ---------------------------------------------------------------------------
// Register-tiled GEMM micro-step. Block = 256 thr. Tile = 64 rows x 128 cols.
// ---------------------------------------------------------------------------
template<int KC, int LDA>
__device__ __forceinline__ void gemm_step(const float* __restrict__ A_s,
                                          const float* __restrict__ B_s,
                                          int m0, int j, float acc[8][4]) {
#pragma unroll 8
    for (int kk = 0; kk < KC; kk++) {
        float4 b = *(const float4*)(B_s + kk * HDIM + j);
#pragma unroll
        for (int r = 0; r < 8; r++) {
            float a = A_s[(m0 + r) * LDA + kk];
            acc[r][0] = fmaf(a, b.x, acc[r][0]);
            acc[r][1] = fmaf(a, b.y, acc[r][1]);
            acc[r][2] = fmaf(a, b.z, acc[r][2]);
            acc[r][3] = fmaf(a, b.w, acc[r][3]);
        }
    }
}

// ---------------------------------------------------------------------------
// Weight fold: g_Wc = W1_e @ Wm[128:256,:],  g_bc = b1_e @ Wm[128:256,:]
// 129 blocks x 128 threads.
// ---------------------------------------------------------------------------
__global__ void k_fold(const float* __restrict__ W1, const float* __restrict__ b1,
                       const float* __restrict__ Wm) {
    __shared__ float a[HDIM];
    int j = threadIdx.x;
    a[j] = (blockIdx.x < 128) ? W1[blockIdx.x * HDIM + j] : b1[j];
    __syncthreads();
    float s = 0.f;
#pragma unroll 8
    for (int l = 0; l < HDIM; l++)
        s = fmaf(a[l], Wm[(HDIM + l) * HDIM + j], s);
    if (blockIdx.x < 128) g_Wc[blockIdx.x * HDIM + j] = s;
    else                  g_bc[j] = s;
}

// ---------------------------------------------------------------------------
// Node encoder: n = relu(x@W0+b0)@W1+b1 ; m_n = n @ Wm_top
// ---------------------------------------------------------------------------
__global__ void k_node_enc(const float* __restrict__ x,
                           const float* __restrict__ W0, const float* __restrict__ b0,
                           const float* __restrict__ W1, const float* __restrict__ b1,
                           const float* __restrict__ Wm) {
    extern __shared__ float sm[];
    float* h_s = sm;                 // [64][132]
    float* B_s = sm + 64 * 132;      // [32][128]
    float* A_s = sm;                 // union, [64][33]

    const int tid = threadIdx.x;
    const int ty = tid >> 5, tx = tid & 31;
    const int m0 = ty * 8;
    const int j  = tx * 4;
    const int row0 = blockIdx.x * 64;

    // layer 1: K = 32
#pragma unroll
    for (int i = 0; i < 8; i++) {
        int idx = tid + i * 256;
        int m = idx >> 5, kk = idx & 31;
        int gr = row0 + m;
        A_s[m * 33 + kk] = (gr < NN) ? x[gr * 32 + kk] : 0.f;
    }
#pragma unroll
    for (int i = 0; i < 16; i++) B_s[tid + i * 256] = W0[tid + i * 256];
    __syncthreads();

    float acc[8][4];
    {
        float4 bv = *(const float4*)(b0 + j);
#pragma unroll
        for (int r = 0; r < 8; r++) { acc[r][0]=bv.x; acc[r][1]=bv.y; acc[r][2]=bv.z; acc[r][3]=bv.w; }
    }
    gemm_step<32, 33>(A_s, B_s, m0, j, acc);
    __syncthreads();

#pragma unroll
    for (int r = 0; r < 8; r++) {
        float4 h;
        h.x = fmaxf(acc[r][0], 0.f); h.y = fmaxf(acc[r][1], 0.f);
        h.z = fmaxf(acc[r][2], 0.f); h.w = fmaxf(acc[r][3], 0.f);
        *(float4*)(h_s + (m0 + r) * 132 + j) = h;
    }

    // layer 2: K = 128
    float o[8][4];
    {
        float4 bv = *(const float4*)(b1 + j);
#pragma unroll
        for (int r = 0; r < 8; r++) { o[r][0]=bv.x; o[r][1]=bv.y; o[r][2]=bv.z; o[r][3]=bv.w; }
    }
    for (int c = 0; c < 4; c++) {
        __syncthreads();
#pragma unroll
        for (int i = 0; i < 16; i++) B_s[tid + i * 256] = W1[c * 32 * 128 + tid + i * 256];
        __syncthreads();
        gemm_step<32, 132>(h_s + c * 32, B_s, m0, j, o);
    }
#pragma unroll
    for (int r = 0; r < 8; r++) {
        int gr = row0 + m0 + r;
        if (gr < NN)
            *(float4*)(g_n + gr * HDIM + j) = make_float4(o[r][0], o[r][1], o[r][2], o[r][3]);
    }

    // m_n = n @ Wm_top  (K = 128)
    __syncthreads();
#pragma unroll
    for (int r = 0; r < 8; r++)
        *(float4*)(h_s + (m0 + r) * 132 + j) = make_float4(o[r][0], o[r][1], o[r][2], o[r][3]);

    float mn[8][4];
#pragma unroll
    for (int r = 0; r < 8; r++) { mn[r][0]=0.f; mn[r][1]=0.f; mn[r][2]=0.f; mn[r][3]=0.f; }
    for (int c = 0; c < 4; c++) {
        __syncthreads();
#pragma unroll
        for (int i = 0; i < 16; i++) B_s[tid + i * 256] = Wm[c * 32 * 128 + tid + i * 256];
        __syncthreads();
        gemm_step<32, 132>(h_s + c * 32, B_s, m0, j, mn);
    }
#pragma unroll
    for (int r = 0; r < 8; r++) {
        int gr = row0 + m0 + r;
        if (gr < NN)
            *(float4*)(g_mn + gr * HDIM + j) = make_float4(mn[r][0], mn[r][1], mn[r][2], mn[r][3]);
    }
}

// ---------------------------------------------------------------------------
// Edge encoder (folded): h = relu(x@W0+b0); g_emsg = h @ g_Wc + g_bc
// ---------------------------------------------------------------------------
__global__ void k_edge_enc(const float* __restrict__ x,
                           const float* __restrict__ W0, const float* __restrict__ b0) {
    extern __shared__ float sm[];
    float* h_s = sm;                 // [64][132]
    float* B_s = sm + 64 * 132;      // [32][128]
    float* A_s = sm;                 // union, [64][17]

    const int tid = threadIdx.x;
    const int ty = tid >> 5, tx = tid & 31;
    const int m0 = ty * 8;
    const int j  = tx * 4;
    const int row0 = blockIdx.x * 64;

    // layer 1: K = 16
#pragma unroll
    for (int i = 0; i < 4; i++) {
        int idx = tid + i * 256;
        int m = idx >> 4, kk = idx & 15;
        A_s[m * 17 + kk] = x[(row0 + m) * 16 + kk];
    }
#pragma unroll
    for (int i = 0; i < 8; i++) B_s[tid + i * 256] = W0[tid + i * 256];
    __syncthreads();

    float acc[8][4];
    {
        float4 bv = *(const float4*)(b0 + j);
#pragma unroll
        for (int r = 0; r < 8; r++) { acc[r][0]=bv.x; acc[r][1]=bv.y; acc[r][2]=bv.z; acc[r][3]=bv.w; }
    }
    gemm_step<16, 17>(A_s, B_s, m0, j, acc);
    __syncthreads();

#pragma unroll
    for (int r = 0; r < 8; r++) {
        float4 h;
        h.x = fmaxf(acc[r][0], 0.f); h.y = fmaxf(acc[r][1], 0.f);
        h.z = fmaxf(acc[r][2], 0.f); h.w = fmaxf(acc[r][3], 0.f);
        *(float4*)(h_s + (m0 + r) * 132 + j) = h;
    }

    // folded layer: K = 128, weights g_Wc, bias g_bc
    float a2[8][4];
    {
        float4 bv = *(const float4*)(g_bc + j);
#pragma unroll
        for (int r = 0; r < 8; r++) { a2[r][0]=bv.x; a2[r][1]=bv.y; a2[r][2]=bv.z; a2[r][3]=bv.w; }
    }
    for (int c = 0; c < 4; c++) {
        __syncthreads();
#pragma unroll
        for (int i = 0; i < 16; i++) B_s[tid + i * 256] = g_Wc[c * 32 * 128 + tid + i * 256];
        __syncthreads();
        gemm_step<32, 132>(h_s + c * 32, B_s, m0, j, a2);
    }
#pragma unroll
    for (int r = 0; r < 8; r++)
        *(float4*)(g_emsg + (row0 + m0 + r) * HDIM + j) =
            make_float4(a2[r][0], a2[r][1], a2[r][2], a2[r][3]);
}

// ---------------------------------------------------------------------------
// Per-pass edge scatter: agg[recv] += m_n[sender] + emsg[e]   (pure memory)
// 1 warp per edge, 8 edges per block.
// ---------------------------------------------------------------------------
__global__ void __launch_bounds__(256) k_edge_scatter(const int* __restrict__ senders,
                                                      const int* __restrict__ recvs) {
    const int e    = blockIdx.x * 8 + (threadIdx.x >> 5);
    const int lane = threadIdx.x & 31;
    const int s = __ldg(senders + e);
    const int r = __ldg(recvs + e);
    const int j = lane * 4;

    float4 m  = *(const float4*)(g_mn   + s * HDIM + j);
    float4 em = *(const float4*)(g_emsg + (long)e * HDIM + j);
    float4 v = make_float4(m.x + em.x, m.y + em.y, m.z + em.z, m.w + em.w);
    float* dst = g_agg + (long)r * HDIM + j;
    asm volatile("red.global.add.v4.f32 [%0], {%1, %2, %3, %4};"
                 :: "l"(dst), "f"(v.x), "f"(v.y), "f"(v.z), "f"(v.w) : "memory");
}

// ---------------------------------------------------------------------------
// Per-pass node update + fused next-pass m_n:
//   h = relu([n|agg]@W0+b0); o = h@W1+b1; n' = LN(n@Wn + o)*g + b
//   if (compute_mn) m_n = n' @ Wm_top
// ---------------------------------------------------------------------------
__global__ void k_node_upd(const float* __restrict__ W0, const float* __restrict__ b0,
                           const float* __restrict__ W1, const float* __restrict__ b1,
                           const float* __restrict__ Wn,
                           const float* __restrict__ lng, const float* __restrict__ lnb,
                           const float* __restrict__ Wm, int compute_mn) {
    extern __shared__ float sm[];
    float* h_s = sm;                 // [64][132]
    float* B_s = sm + 64 * 132;      // [32][128]
    float* A_s = sm;                 // union, [64][33]

    const int tid = threadIdx.x;
    const int ty = tid >> 5, tx = tid & 31;
    const int m0 = ty * 8;
    const int j  = tx * 4;
    const int row0 = blockIdx.x * 64;

    // hidden: K = 256
    float acc[8][4];
    {
        float4 bv = *(const float4*)(b0 + j);
#pragma unroll
        for (int r = 0; r < 8; r++) { acc[r][0]=bv.x; acc[r][1]=bv.y; acc[r][2]=bv.z; acc[r][3]=bv.w; }
    }
    for (int c = 0; c < 8; c++) {
        const float* src = (c < 4) ? g_n : g_agg;
        int koff = (c & 3) * 32;
        __syncthreads();
#pragma unroll
        for (int i = 0; i < 8; i++) {
            int idx = tid + i * 256;
            int m = idx >> 5, kk = idx & 31;
            int gr = row0 + m;
            A_s[m * 33 + kk] = (gr < NN) ? src[gr * HDIM + koff + kk] : 0.f;
        }
#pragma unroll
        for (int i = 0; i < 16; i++) B_s[tid + i * 256] = W0[c * 32 * 128 + tid + i * 256];
        __syncthreads();
        gemm_step<32, 33>(A_s, B_s, m0, j, acc);
    }
    __syncthreads();
#pragma unroll
    for (int r = 0; r < 8; r++) {
        float4 h;
        h.x = fmaxf(acc[r][0], 0.f); h.y = fmaxf(acc[r][1], 0.f);
        h.z = fmaxf(acc[r][2], 0.f); h.w = fmaxf(acc[r][3], 0.f);
        *(float4*)(h_s + (m0 + r) * 132 + j) = h;
    }

    // output: K = 128
    float o[8][4];
    {
        float4 bv = *(const float4*)(b1 + j);
#pragma unroll
        for (int r = 0; r < 8; r++) { o[r][0]=bv.x; o[r][1]=bv.y; o[r][2]=bv.z; o[r][3]=bv.w; }
    }
    for (int c = 0; c < 4; c++) {
        __syncthreads();
#pragma unroll
        for (int i = 0; i < 16; i++) B_s[tid + i * 256] = W1[c * 32 * 128 + tid + i * 256];
        __syncthreads();
        gemm_step<32, 132>(h_s + c * 32, B_s, m0, j, o);
    }

    // residual: n @ Wn, K = 128
    float rr[8][4];
#pragma unroll
    for (int r = 0; r < 8; r++) { rr[r][0]=0.f; rr[r][1]=0.f; rr[r][2]=0.f; rr[r][3]=0.f; }
    for (int c = 0; c < 4; c++) {
        __syncthreads();
#pragma unroll
        for (int i = 0; i < 8; i++) {
            int idx = tid + i * 256;
            int m = idx >> 5, kk = idx & 31;
            int gr = row0 + m;
            A_s[m * 33 + kk] = (gr < NN) ? g_n[gr * HDIM + c * 32 + kk] : 0.f;
        }
#pragma unroll
        for (int i = 0; i < 16; i++) B_s[tid + i * 256] = Wn[c * 32 * 128 + tid + i * 256];
        __syncthreads();
        gemm_step<32, 33>(A_s, B_s, m0, j, rr);
    }

    // LayerNorm epilogue
    float4 gv  = *(const float4*)(lng + j);
    float4 bbv = *(const float4*)(lnb + j);
    float nn[8][4];
#pragma unroll
    for (int r = 0; r < 8; r++) {
        float t0 = o[r][0] + rr[r][0];
        float t1 = o[r][1] + rr[r][1];
        float t2 = o[r][2] + rr[r][2];
        float t3 = o[r][3] + rr[r][3];
        float s1 = t0 + t1 + t2 + t3;
        float s2 = t0*t0 + t1*t1 + t2*t2 + t3*t3;
#pragma unroll
        for (int off = 16; off > 0; off >>= 1) {
            s1 += __shfl_xor_sync(0xffffffffu, s1, off);
            s2 += __shfl_xor_sync(0xffffffffu, s2, off);
        }
        float mu  = s1 * (1.f / 128.f);
        float var = s2 * (1.f / 128.f) - mu * mu;
        float inv = rsqrtf(var + LN_EPS);
        nn[r][0] = (t0 - mu) * inv * gv.x + bbv.x;
        nn[r][1] = (t1 - mu) * inv * gv.y + bbv.y;
        nn[r][2] = (t2 - mu) * inv * gv.z + bbv.z;
        nn[r][3] = (t3 - mu) * inv * gv.w + bbv.w;
        int gr = row0 + m0 + r;
        if (gr < NN)
            *(float4*)(g_n + gr * HDIM + j) = make_float4(nn[r][0], nn[r][1], nn[r][2], nn[r][3]);
    }

    if (!compute_mn) return;

    // m_n = n' @ Wm_top  (K = 128)
    __syncthreads();
#pragma unroll
    for (int r = 0; r < 8; r++)
        *(float4*)(h_s + (m0 + r) * 132 + j) = make_float4(nn[r][0], nn[r][1], nn[r][2], nn[r][3]);

    float mn[8][4];
#pragma unroll
    for (int r = 0; r < 8; r++) { mn[r][0]=0.f; mn[r][1]=0.f; mn[r][2]=0.f; mn[r][3]=0.f; }
    for (int c = 0; c < 4; c++) {
        __syncthreads();
#pragma unroll
        for (int i = 0; i < 16; i++) B_s[tid + i * 256] = Wm[c * 32 * 128 + tid + i * 256];
        __syncthreads();
        gemm_step<32, 132>(h_s + c * 32, B_s, m0, j, mn);
    }
#pragma unroll
    for (int r = 0; r < 8; r++) {
        int gr = row0 + m0 + r;
        if (gr < NN)
            *(float4*)(g_mn + gr * HDIM + j) = make_float4(mn[r][0], mn[r][1], mn[r][2], mn[r][3]);
    }
}

// ---------------------------------------------------------------------------
// Decoder: out = relu(n @ W0 + b0) @ W1 + b1       out: [NN,2]
// ---------------------------------------------------------------------------
__global__ void k_dec(const float* __restrict__ W0, const float* __restrict__ b0,
                      const float* __restrict__ W1, const float* __restrict__ b1,
                      float* __restrict__ out) {
    extern __shared__ float sm[];
    float* h_s  = sm;                 // [64][132]
    float* B_s  = sm + 64 * 132;      // [32][128]
    float* A_s  = sm;                 // union, [64][33]
    float* w1_s = B_s + 32 * 128;     // [128*2]
    float* b1_s = w1_s + 256;         // [2]

    const int tid = threadIdx.x;
    const int ty = tid >> 5, tx = tid & 31;
    const int m0 = ty * 8;
    const int j  = tx * 4;
    const int row0 = blockIdx.x * 64;

    float acc[8][4];
    {
        float4 bv = *(const float4*)(b0 + j);
#pragma unroll
        for (int r = 0; r < 8; r++) { acc[r][0]=bv.x; acc[r][1]=bv.y; acc[r][2]=bv.z; acc[r][3]=bv.w; }
    }
    for (int c = 0; c < 4; c++) {
        __syncthreads();
#pragma unroll
        for (int i = 0; i < 8; i++) {
            int idx = tid + i * 256;
            int m = idx >> 5, kk = idx & 31;
            int gr = row0 + m;
            A_s[m * 33 + kk] = (gr < NN) ? g_n[gr * HDIM + c * 32 + kk] : 0.f;
        }
#pragma unroll
        for (int i = 0; i < 16; i++) B_s[tid + i * 256] = W0[c * 32 * 128 + tid + i * 256];
        __syncthreads();
        gemm_step<32, 33>(A_s, B_s, m0, j, acc);
    }
    __syncthreads();
#pragma unroll
    for (int r = 0; r < 8; r++) {
        float4 h;
        h.x = fmaxf(acc[r][0], 0.f); h.y = fmaxf(acc[r][1], 0.f);
        h.z = fmaxf(acc[r][2], 0.f); h.w = fmaxf(acc[r][3], 0.f);
        *(float4*)(h_s + (m0 + r) * 132 + j) = h;
    }
    w1_s[tid] = W1[tid];
    if (tid < 2) b1_s[tid] = b1[tid];
    __syncthreads();

    if (tid < 128) {
        int row = tid >> 1, c = tid & 1;
        float s = b1_s[c];
#pragma unroll 8
        for (int k = 0; k < 128; k++)
            s = fmaf(h_s[row * 132 + k], w1_s[k * 2 + c], s);
        int gr = row0 + row;
        if (gr < NN) out[gr * 2 + c] = s;
    }
}

__global__ void k_zero_agg() {
    int i = blockIdx.x * blockDim.x + threadIdx.x;
    if (i < NN * HDIM / 4)
        ((float4*)g_agg)[i] = make_float4(0.f, 0.f, 0.f, 0.f);
}

// ---------------------------------------------------------------------------
extern "C" void kernel_launch(void* const* d_in, const int* in_sizes, int n_in,
                              void* d_out, int out_size) {
    const float* nodes   = (const float*)d_in[0];
    const float* edges   = (const float*)d_in[1];
    const int*   senders = (const int*)  d_in[2];
    const int*   recvs   = (const int*)  d_in[3];
    const float* enW0 = (const float*)d_in[4];
    const float* enb0 = (const float*)d_in[5];
    const float* enW1 = (const float*)d_in[6];
    const float* enb1 = (const float*)d_in[7];
    const float* eeW0 = (const float*)d_in[8];
    const float* eeb0 = (const float*)d_in[9];
    const float* eeW1 = (const float*)d_in[10];
    const float* eeb1 = (const float*)d_in[11];
    const float* Wmsg = (const float*)d_in[12];
    const float* nW0  = (const float*)d_in[13];
    const float* nb0  = (const float*)d_in[14];
    const float* nW1  = (const float*)d_in[15];
    const float* nb1  = (const float*)d_in[16];
    const float* Wnode= (const float*)d_in[17];
    const float* lng  = (const float*)d_in[18];
    const float* lnb  = (const float*)d_in[19];
    const float* dW0  = (const float*)d_in[20];
    const float* db0  = (const float*)d_in[21];
    const float* dW1  = (const float*)d_in[22];
    const float* db1  = (const float*)d_in[23];
    float* out = (float*)d_out;

    const int SM_BIG = (64 * 132 + 32 * 128) * 4;              // 50176 B
    const int SM_DEC = (64 * 132 + 32 * 128 + 256 + 2) * 4;    // 51208 B

    cudaFuncSetAttribute(k_node_enc, cudaFuncAttributeMaxDynamicSharedMemorySize, SM_BIG);
    cudaFuncSetAttribute(k_edge_enc, cudaFuncAttributeMaxDynamicSharedMemorySize, SM_BIG);
    cudaFuncSetAttribute(k_node_upd, cudaFuncAttributeMaxDynamicSharedMemorySize, SM_BIG);
    cudaFuncSetAttribute(k_dec,      cudaFuncAttributeMaxDynamicSharedMemorySize, SM_DEC);

    k_fold<<<129, 128>>>(eeW1, eeb1, Wmsg);
    k_node_enc<<<NODE_TILES, 256, SM_BIG>>>(nodes, enW0, enb0, enW1, enb1, Wmsg);
    k_edge_enc<<<EDGE_TILES, 256, SM_BIG>>>(edges, eeW0, eeb0);

    for (int p = 0; p < NPASS; p++) {
        k_zero_agg<<<(NN * HDIM / 4 + 255) / 256, 256>>>();
        k_edge_scatter<<<NEDGE / 8, 256>>>(senders, recvs);
        k_node_upd<<<NODE_TILES, 256, SM_BIG>>>(nW0, nb0, nW1, nb1, Wnode, lng, lnb,
                                                Wmsg, p < NPASS - 1 ? 1 : 0);
    }

    k_dec<<<NODE_TILES, 256, SM_DEC>>>(dW0, db0, dW1, db1, out);
}

// round 3
// speedup vs baseline: 3.3132x; 1.4606x over previous
#include <cuda_runtime.h>
#include <math.h>

#define NN     50000
#define NEDGE  600000
#define HDIM   128
#define NPASS  5
#define LN_EPS 1e-6f

#define NODE_TILES ((NN + 63) / 64)   // 782
#define EDGE_TILES (NEDGE / 64)       // 9375 (exact)

// Persistent device scratch
__device__ float g_n[NN * HDIM];        // node features
__device__ float g_S[NN * HDIM];        // per-pass scatter of n[sender]
__device__ float g_hsum[NN * HDIM];     // sum of edge hidden h over receivers
__device__ float g_deg[NN];             // in-degree (float)
__device__ float g_cagg[NN * HDIM];     // loop-invariant agg contribution @ W0_bot
__device__ float g_T1[HDIM * HDIM];     // W1e @ Wm_bot
__device__ float g_tvec[HDIM];          // b1e @ Wm_bot
__device__ float g_Wg[HDIM * HDIM];     // W1e @ Wm_bot @ W0_bot
__device__ float g_bg[HDIM];            // b1e @ Wm_bot @ W0_bot
__device__ float g_Wf[HDIM * HDIM];     // Wm_top @ W0_bot

// ---------------------------------------------------------------------------
// Register-tiled GEMM micro-step. Block = 256 thr. Tile = 64 rows x 128 cols.
// ---------------------------------------------------------------------------
template<int KC, int LDA>
__device__ __forceinline__ void gemm_step(const float* __restrict__ A_s,
                                          const float* __restrict__ B_s,
                                          int m0, int j, float acc[8][4]) {
#pragma unroll 8
    for (int kk = 0; kk < KC; kk++) {
        float4 b = *(const float4*)(B_s + kk * HDIM + j);
#pragma unroll
        for (int r = 0; r < 8; r++) {
            float a = A_s[(m0 + r) * LDA + kk];
            acc[r][0] = fmaf(a, b.x, acc[r][0]);
            acc[r][1] = fmaf(a, b.y, acc[r][1]);
            acc[r][2] = fmaf(a, b.z, acc[r][2]);
            acc[r][3] = fmaf(a, b.w, acc[r][3]);
        }
    }
}

// ---------------------------------------------------------------------------
// Weight folds
// ---------------------------------------------------------------------------
__global__ void k_fold1(const float* __restrict__ W1e, const float* __restrict__ b1e,
                        const float* __restrict__ Wm) {
    __shared__ float a[HDIM];
    int j = threadIdx.x;
    a[j] = (blockIdx.x < 128) ? W1e[blockIdx.x * HDIM + j] : b1e[j];
    __syncthreads();
    float s = 0.f;
#pragma unroll 8
    for (int l = 0; l < HDIM; l++)
        s = fmaf(a[l], Wm[(HDIM + l) * HDIM + j], s);
    if (blockIdx.x < 128) g_T1[blockIdx.x * HDIM + j] = s;
    else                  g_tvec[j] = s;
}

__global__ void k_fold2(const float* __restrict__ W0n, const float* __restrict__ Wm) {
    __shared__ float a[HDIM];
    int j = threadIdx.x;
    int bid = blockIdx.x;
    if (bid < 128)       a[j] = g_T1[bid * HDIM + j];
    else if (bid == 128) a[j] = g_tvec[j];
    else                 a[j] = Wm[(bid - 129) * HDIM + j];   // Wm_top rows
    __syncthreads();
    float s = 0.f;
#pragma unroll 8
    for (int l = 0; l < HDIM; l++)
        s = fmaf(a[l], W0n[(HDIM + l) * HDIM + j], s);        // W0_bot
    if (bid < 128)       g_Wg[bid * HDIM + j] = s;
    else if (bid == 128) g_bg[j] = s;
    else                 g_Wf[(bid - 129) * HDIM + j] = s;
}

// ---------------------------------------------------------------------------
// Zero helpers
// ---------------------------------------------------------------------------
__global__ void k_zero_pre() {   // zero g_hsum and g_deg
    int i = blockIdx.x * blockDim.x + threadIdx.x;
    if (i < NN * 32) ((float4*)g_hsum)[i] = make_float4(0.f, 0.f, 0.f, 0.f);
    else {
        int d = i - NN * 32;
        if (d < NN / 4) ((float4*)g_deg)[d] = make_float4(0.f, 0.f, 0.f, 0.f);
    }
}
__global__ void k_zero_S() {
    int i = blockIdx.x * blockDim.x + threadIdx.x;
    if (i < NN * 32) ((float4*)g_S)[i] = make_float4(0.f, 0.f, 0.f, 0.f);
}

// ---------------------------------------------------------------------------
// Node encoder: n = relu(x@W0+b0)@W1+b1
// ---------------------------------------------------------------------------
__global__ void k_node_enc(const float* __restrict__ x,
                           const float* __restrict__ W0, const float* __restrict__ b0,
                           const float* __restrict__ W1, const float* __restrict__ b1) {
    extern __shared__ float sm[];
    float* h_s = sm;                 // [64][132]
    float* B_s = sm + 64 * 132;      // [32][128]
    float* A_s = sm;                 // union, [64][33]

    const int tid = threadIdx.x;
    const int ty = tid >> 5, tx = tid & 31;
    const int m0 = ty * 8;
    const int j  = tx * 4;
    const int row0 = blockIdx.x * 64;

#pragma unroll
    for (int i = 0; i < 8; i++) {
        int idx = tid + i * 256;
        int m = idx >> 5, kk = idx & 31;
        int gr = row0 + m;
        A_s[m * 33 + kk] = (gr < NN) ? x[gr * 32 + kk] : 0.f;
    }
#pragma unroll
    for (int i = 0; i < 16; i++) B_s[tid + i * 256] = W0[tid + i * 256];
    __syncthreads();

    float acc[8][4];
    {
        float4 bv = *(const float4*)(b0 + j);
#pragma unroll
        for (int r = 0; r < 8; r++) { acc[r][0]=bv.x; acc[r][1]=bv.y; acc[r][2]=bv.z; acc[r][3]=bv.w; }
    }
    gemm_step<32, 33>(A_s, B_s, m0, j, acc);
    __syncthreads();

#pragma unroll
    for (int r = 0; r < 8; r++) {
        float4 h;
        h.x = fmaxf(acc[r][0], 0.f); h.y = fmaxf(acc[r][1], 0.f);
        h.z = fmaxf(acc[r][2], 0.f); h.w = fmaxf(acc[r][3], 0.f);
        *(float4*)(h_s + (m0 + r) * 132 + j) = h;
    }

    float o[8][4];
    {
        float4 bv = *(const float4*)(b1 + j);
#pragma unroll
        for (int r = 0; r < 8; r++) { o[r][0]=bv.x; o[r][1]=bv.y; o[r][2]=bv.z; o[r][3]=bv.w; }
    }
    for (int c = 0; c < 4; c++) {
        __syncthreads();
#pragma unroll
        for (int i = 0; i < 16; i++) B_s[tid + i * 256] = W1[c * 32 * 128 + tid + i * 256];
        __syncthreads();
        gemm_step<32, 132>(h_s + c * 32, B_s, m0, j, o);
    }
#pragma unroll
    for (int r = 0; r < 8; r++) {
        int gr = row0 + m0 + r;
        if (gr < NN)
            *(float4*)(g_n + gr * HDIM + j) = make_float4(o[r][0], o[r][1], o[r][2], o[r][3]);
    }
}

// ---------------------------------------------------------------------------
// Edge encoder + scatter: h = relu(x@W0+b0); g_hsum[recv] += h; g_deg[recv] += 1
// ---------------------------------------------------------------------------
__global__ void __launch_bounds__(256) k_edge_enc_scatter(
        const float* __restrict__ x,
        const float* __restrict__ W0, const float* __restrict__ b0,
        const int* __restrict__ recvs) {
    __shared__ float A_s[64 * 17];
    __shared__ float B_s[16 * 128];
    __shared__ int   r_idx[64];

    const int tid = threadIdx.x;
    const int ty = tid >> 5, tx = tid & 31;
    const int m0 = ty * 8;
    const int j  = tx * 4;
    const int row0 = blockIdx.x * 64;

#pragma unroll
    for (int i = 0; i < 4; i++) {
        int idx = tid + i * 256;
        int m = idx >> 4, kk = idx & 15;
        A_s[m * 17 + kk] = x[(row0 + m) * 16 + kk];
    }
#pragma unroll
    for (int i = 0; i < 8; i++) B_s[tid + i * 256] = W0[tid + i * 256];
    if (tid < 64) r_idx[tid] = recvs[row0 + tid];
    __syncthreads();

    float acc[8][4];
    {
        float4 bv = *(const float4*)(b0 + j);
#pragma unroll
        for (int r = 0; r < 8; r++) { acc[r][0]=bv.x; acc[r][1]=bv.y; acc[r][2]=bv.z; acc[r][3]=bv.w; }
    }
    gemm_step<16, 17>(A_s, B_s, m0, j, acc);

#pragma unroll
    for (int r = 0; r < 8; r++) {
        int row = m0 + r;
        int rv = r_idx[row];
        float v0 = fmaxf(acc[r][0], 0.f), v1 = fmaxf(acc[r][1], 0.f);
        float v2 = fmaxf(acc[r][2], 0.f), v3 = fmaxf(acc[r][3], 0.f);
        float* dst = g_hsum + (long)rv * HDIM + j;
        asm volatile("red.global.add.v4.f32 [%0], {%1, %2, %3, %4};"
                     :: "l"(dst), "f"(v0), "f"(v1), "f"(v2), "f"(v3) : "memory");
        if (tx == 0) atomicAdd(g_deg + rv, 1.0f);
    }
}

// ---------------------------------------------------------------------------
// c_agg = g_hsum @ g_Wg + g_deg * g_bg
// ---------------------------------------------------------------------------
__global__ void k_cagg() {
    extern __shared__ float sm[];
    float* A_s = sm;                 // [64][33]
    float* B_s = sm + 64 * 33;       // [32][128]

    const int tid = threadIdx.x;
    const int ty = tid >> 5, tx = tid & 31;
    const int m0 = ty * 8;
    const int j  = tx * 4;
    const int row0 = blockIdx.x * 64;

    float acc[8][4];
    {
        float4 bgv = *(const float4*)(g_bg + j);
#pragma unroll
        for (int r = 0; r < 8; r++) {
            int gr = row0 + m0 + r;
            float d = (gr < NN) ? g_deg[gr] : 0.f;
            acc[r][0] = d * bgv.x; acc[r][1] = d * bgv.y;
            acc[r][2] = d * bgv.z; acc[r][3] = d * bgv.w;
        }
    }
    for (int c = 0; c < 4; c++) {
        __syncthreads();
#pragma unroll
        for (int i = 0; i < 8; i++) {
            int idx = tid + i * 256;
            int m = idx >> 5, kk = idx & 31;
            int gr = row0 + m;
            A_s[m * 33 + kk] = (gr < NN) ? g_hsum[gr * HDIM + c * 32 + kk] : 0.f;
        }
#pragma unroll
        for (int i = 0; i < 16; i++) B_s[tid + i * 256] = g_Wg[c * 32 * 128 + tid + i * 256];
        __syncthreads();
        gemm_step<32, 33>(A_s, B_s, m0, j, acc);
    }
#pragma unroll
    for (int r = 0; r < 8; r++) {
        int gr = row0 + m0 + r;
        if (gr < NN)
            *(float4*)(g_cagg + gr * HDIM + j) =
                make_float4(acc[r][0], acc[r][1], acc[r][2], acc[r][3]);
    }
}

// ---------------------------------------------------------------------------
// Per-pass scatter: S[recv] += n[sender]    (pure L2 gather/atomic)
// ---------------------------------------------------------------------------
__global__ void __launch_bounds__(256) k_scatter_n(const int* __restrict__ senders,
                                                   const int* __restrict__ recvs) {
    const int e    = blockIdx.x * 8 + (threadIdx.x >> 5);
    const int lane = threadIdx.x & 31;
    const int j = lane * 4;
    const int s = __ldg(senders + e);
    const int r = __ldg(recvs + e);
    float4 v = *(const float4*)(g_n + (long)s * HDIM + j);
    float* dst = g_S + (long)r * HDIM + j;
    asm volatile("red.global.add.v4.f32 [%0], {%1, %2, %3, %4};"
                 :: "l"(dst), "f"(v.x), "f"(v.y), "f"(v.z), "f"(v.w) : "memory");
}

// ---------------------------------------------------------------------------
// Per-pass node update:
//   h = relu(n@W0_top + S@Wf + c_agg + b0); o = h@W1+b1; n' = LN(n@Wn + o)*g+b
// ---------------------------------------------------------------------------
__global__ void k_node_upd(const float* __restrict__ W0, const float* __restrict__ b0,
                           const float* __restrict__ W1, const float* __restrict__ b1,
                           const float* __restrict__ Wn,
                           const float* __restrict__ lng, const float* __restrict__ lnb) {
    extern __shared__ float sm[];
    float* h_s = sm;                 // [64][132]
    float* B_s = sm + 64 * 132;      // [32][128]
    float* A_s = sm;                 // union, [64][33]

    const int tid = threadIdx.x;
    const int ty = tid >> 5, tx = tid & 31;
    const int m0 = ty * 8;
    const int j  = tx * 4;
    const int row0 = blockIdx.x * 64;

    // hidden: K = 256 over [n | S], weights [W0_top ; Wf], init b0 + c_agg
    float acc[8][4];
    {
        float4 bv = *(const float4*)(b0 + j);
#pragma unroll
        for (int r = 0; r < 8; r++) {
            int gr = row0 + m0 + r;
            float4 cv = (gr < NN) ? *(const float4*)(g_cagg + gr * HDIM + j)
                                  : make_float4(0.f, 0.f, 0.f, 0.f);
            acc[r][0] = bv.x + cv.x; acc[r][1] = bv.y + cv.y;
            acc[r][2] = bv.z + cv.z; acc[r][3] = bv.w + cv.w;
        }
    }
    for (int c = 0; c < 8; c++) {
        const float* src = (c < 4) ? g_n : g_S;
        const float* Bsrc = (c < 4) ? (W0 + c * 32 * 128) : (g_Wf + (c - 4) * 32 * 128);
        int koff = (c & 3) * 32;
        __syncthreads();
#pragma unroll
        for (int i = 0; i < 8; i++) {
            int idx = tid + i * 256;
            int m = idx >> 5, kk = idx & 31;
            int gr = row0 + m;
            A_s[m * 33 + kk] = (gr < NN) ? src[gr * HDIM + koff + kk] : 0.f;
        }
#pragma unroll
        for (int i = 0; i < 16; i++) B_s[tid + i * 256] = Bsrc[tid + i * 256];
        __syncthreads();
        gemm_step<32, 33>(A_s, B_s, m0, j, acc);
    }
    __syncthreads();
#pragma unroll
    for (int r = 0; r < 8; r++) {
        float4 h;
        h.x = fmaxf(acc[r][0], 0.f); h.y = fmaxf(acc[r][1], 0.f);
        h.z = fmaxf(acc[r][2], 0.f); h.w = fmaxf(acc[r][3], 0.f);
        *(float4*)(h_s + (m0 + r) * 132 + j) = h;
    }

    // output: K = 128
    float o[8][4];
    {
        float4 bv = *(const float4*)(b1 + j);
#pragma unroll
        for (int r = 0; r < 8; r++) { o[r][0]=bv.x; o[r][1]=bv.y; o[r][2]=bv.z; o[r][3]=bv.w; }
    }
    for (int c = 0; c < 4; c++) {
        __syncthreads();
#pragma unroll
        for (int i = 0; i < 16; i++) B_s[tid + i * 256] = W1[c * 32 * 128 + tid + i * 256];
        __syncthreads();
        gemm_step<32, 132>(h_s + c * 32, B_s, m0, j, o);
    }

    // residual: n @ Wn, K = 128
    float rr[8][4];
#pragma unroll
    for (int r = 0; r < 8; r++) { rr[r][0]=0.f; rr[r][1]=0.f; rr[r][2]=0.f; rr[r][3]=0.f; }
    for (int c = 0; c < 4; c++) {
        __syncthreads();
#pragma unroll
        for (int i = 0; i < 8; i++) {
            int idx = tid + i * 256;
            int m = idx >> 5, kk = idx & 31;
            int gr = row0 + m;
            A_s[m * 33 + kk] = (gr < NN) ? g_n[gr * HDIM + c * 32 + kk] : 0.f;
        }
#pragma unroll
        for (int i = 0; i < 16; i++) B_s[tid + i * 256] = Wn[c * 32 * 128 + tid + i * 256];
        __syncthreads();
        gemm_step<32, 33>(A_s, B_s, m0, j, rr);
    }

    // LayerNorm epilogue
    float4 gv  = *(const float4*)(lng + j);
    float4 bbv = *(const float4*)(lnb + j);
#pragma unroll
    for (int r = 0; r < 8; r++) {
        float t0 = o[r][0] + rr[r][0];
        float t1 = o[r][1] + rr[r][1];
        float t2 = o[r][2] + rr[r][2];
        float t3 = o[r][3] + rr[r][3];
        float s1 = t0 + t1 + t2 + t3;
        float s2 = t0*t0 + t1*t1 + t2*t2 + t3*t3;
#pragma unroll
        for (int off = 16; off > 0; off >>= 1) {
            s1 += __shfl_xor_sync(0xffffffffu, s1, off);
            s2 += __shfl_xor_sync(0xffffffffu, s2, off);
        }
        float mu  = s1 * (1.f / 128.f);
        float var = s2 * (1.f / 128.f) - mu * mu;
        float inv = rsqrtf(var + LN_EPS);
        int gr = row0 + m0 + r;
        if (gr < NN) {
            float4 out;
            out.x = (t0 - mu) * inv * gv.x + bbv.x;
            out.y = (t1 - mu) * inv * gv.y + bbv.y;
            out.z = (t2 - mu) * inv * gv.z + bbv.z;
            out.w = (t3 - mu) * inv * gv.w + bbv.w;
            *(float4*)(g_n + gr * HDIM + j) = out;
        }
    }
}

// ---------------------------------------------------------------------------
// Decoder: out = relu(n @ W0 + b0) @ W1 + b1       out: [NN,2]
// ---------------------------------------------------------------------------
__global__ void k_dec(const float* __restrict__ W0, const float* __restrict__ b0,
                      const float* __restrict__ W1, const float* __restrict__ b1,
                      float* __restrict__ out) {
    extern __shared__ float sm[];
    float* h_s  = sm;                 // [64][132]
    float* B_s  = sm + 64 * 132;      // [32][128]
    float* A_s  = sm;                 // union, [64][33]
    float* w1_s = B_s + 32 * 128;     // [128*2]
    float* b1_s = w1_s + 256;         // [2]

    const int tid = threadIdx.x;
    const int ty = tid >> 5, tx = tid & 31;
    const int m0 = ty * 8;
    const int j  = tx * 4;
    const int row0 = blockIdx.x * 64;

    float acc[8][4];
    {
        float4 bv = *(const float4*)(b0 + j);
#pragma unroll
        for (int r = 0; r < 8; r++) { acc[r][0]=bv.x; acc[r][1]=bv.y; acc[r][2]=bv.z; acc[r][3]=bv.w; }
    }
    for (int c = 0; c < 4; c++) {
        __syncthreads();
#pragma unroll
        for (int i = 0; i < 8; i++) {
            int idx = tid + i * 256;
            int m = idx >> 5, kk = idx & 31;
            int gr = row0 + m;
            A_s[m * 33 + kk] = (gr < NN) ? g_n[gr * HDIM + c * 32 + kk] : 0.f;
        }
#pragma unroll
        for (int i = 0; i < 16; i++) B_s[tid + i * 256] = W0[c * 32 * 128 + tid + i * 256];
        __syncthreads();
        gemm_step<32, 33>(A_s, B_s, m0, j, acc);
    }
    __syncthreads();
#pragma unroll
    for (int r = 0; r < 8; r++) {
        float4 h;
        h.x = fmaxf(acc[r][0], 0.f); h.y = fmaxf(acc[r][1], 0.f);
        h.z = fmaxf(acc[r][2], 0.f); h.w = fmaxf(acc[r][3], 0.f);
        *(float4*)(h_s + (m0 + r) * 132 + j) = h;
    }
    w1_s[tid] = W1[tid];
    if (tid < 2) b1_s[tid] = b1[tid];
    __syncthreads();

    if (tid < 128) {
        int row = tid >> 1, c = tid & 1;
        float s = b1_s[c];
#pragma unroll 8
        for (int k = 0; k < 128; k++)
            s = fmaf(h_s[row * 132 + k], w1_s[k * 2 + c], s);
        int gr = row0 + row;
        if (gr < NN) out[gr * 2 + c] = s;
    }
}

// ---------------------------------------------------------------------------
extern "C" void kernel_launch(void* const* d_in, const int* in_sizes, int n_in,
                              void* d_out, int out_size) {
    const float* nodes   = (const float*)d_in[0];
    const float* edges   = (const float*)d_in[1];
    const int*   senders = (const int*)  d_in[2];
    const int*   recvs   = (const int*)  d_in[3];
    const float* enW0 = (const float*)d_in[4];
    const float* enb0 = (const float*)d_in[5];
    const float* enW1 = (const float*)d_in[6];
    const float* enb1 = (const float*)d_in[7];
    const float* eeW0 = (const float*)d_in[8];
    const float* eeb0 = (const float*)d_in[9];
    const float* eeW1 = (const float*)d_in[10];
    const float* eeb1 = (const float*)d_in[11];
    const float* Wmsg = (const float*)d_in[12];
    const float* nW0  = (const float*)d_in[13];
    const float* nb0  = (const float*)d_in[14];
    const float* nW1  = (const float*)d_in[15];
    const float* nb1  = (const float*)d_in[16];
    const float* Wnode= (const float*)d_in[17];
    const float* lng  = (const float*)d_in[18];
    const float* lnb  = (const float*)d_in[19];
    const float* dW0  = (const float*)d_in[20];
    const float* db0  = (const float*)d_in[21];
    const float* dW1  = (const float*)d_in[22];
    const float* db1  = (const float*)d_in[23];
    float* out = (float*)d_out;

    const int SM_BIG = (64 * 132 + 32 * 128) * 4;              // 50176 B
    const int SM_MSG = (64 * 33 + 32 * 128) * 4;               // 24832 B
    const int SM_DEC = (64 * 132 + 32 * 128 + 256 + 2) * 4;    // 51208 B

    cudaFuncSetAttribute(k_node_enc, cudaFuncAttributeMaxDynamicSharedMemorySize, SM_BIG);
    cudaFuncSetAttribute(k_cagg,     cudaFuncAttributeMaxDynamicSharedMemorySize, SM_MSG);
    cudaFuncSetAttribute(k_node_upd, cudaFuncAttributeMaxDynamicSharedMemorySize, SM_BIG);
    cudaFuncSetAttribute(k_dec,      cudaFuncAttributeMaxDynamicSharedMemorySize, SM_DEC);

    // Folds + invariants
    k_fold1<<<129, 128>>>(eeW1, eeb1, Wmsg);
    k_fold2<<<257, 128>>>(nW0, Wmsg);
    k_zero_pre<<<(NN * 32 + NN / 4 + 255) / 256, 256>>>();
    k_node_enc<<<NODE_TILES, 256, SM_BIG>>>(nodes, enW0, enb0, enW1, enb1);
    k_edge_enc_scatter<<<EDGE_TILES, 256>>>(edges, eeW0, eeb0, recvs);
    k_cagg<<<NODE_TILES, 256, SM_MSG>>>();

    for (int p = 0; p < NPASS; p++) {
        k_zero_S<<<(NN * 32 + 255) / 256, 256>>>();
        k_scatter_n<<<NEDGE / 8, 256>>>(senders, recvs);
        k_node_upd<<<NODE_TILES, 256, SM_BIG>>>(nW0, nb0, nW1, nb1, Wnode, lng, lnb);
    }

    k_dec<<<NODE_TILES, 256, SM_DEC>>>(dW0, db0, dW1, db1, out);
}